// round 7
// baseline (speedup 1.0000x reference)
#include <cuda_runtime.h>

typedef unsigned long long u64;
typedef unsigned int u32;

// ---- packed fp32x2 helpers (backward path only) ----
__device__ __forceinline__ u64 fma2(u64 a, u64 b, u64 c) {
    u64 d; asm("fma.rn.f32x2 %0, %1, %2, %3;" : "=l"(d) : "l"(a), "l"(b), "l"(c)); return d;
}
__device__ __forceinline__ u64 add2(u64 a, u64 b) {
    u64 d; asm("add.rn.f32x2 %0, %1, %2;" : "=l"(d) : "l"(a), "l"(b)); return d;
}
__device__ __forceinline__ u64 pack2(float lo, float hi) {
    u64 d; asm("mov.b64 %0, {%1, %2};" : "=l"(d) : "f"(lo), "f"(hi)); return d;
}
__device__ __forceinline__ float lo2(u64 v) { return __uint_as_float((u32)v); }
__device__ __forceinline__ float hi2(u64 v) { return __uint_as_float((u32)(v >> 32)); }

// Dynamic smem layout (floats):
//   [0, 12288)       : weights, 3 layers x 64x64 (t-column stripped)
//   [12288, 12480)   : w0sh = t * W[j][0] per layer (serial-chain init term)
//   [12480, 12672)   : bsh  = biases per layer (added AFTER the k-sum, like XLA)
//   [12672, ...)     : h-buffer, u64[32 pairs][128 threads]  (32 KB)
extern __shared__ float smf[];

// Forward layer, ORDER-MATCHED to cuBLAS SGEMM: per output j, a single
// accumulator initialized to rn(t*W[j][0]) then 64 serial FMAs with k
// ascending, bias added after the sum, then relu. 4 independent j-chains are
// interleaved for ILP. j-loop rolled; h is a scalar register array indexed
// only by compile-time constants (unrolled i-loop) — spill-safe.
template<bool RELU>
__device__ __forceinline__ void fwd_serial(const float* __restrict__ Wl,
                                           const float* __restrict__ w0l,
                                           const float* __restrict__ bl,
                                           const float* h, float* hb_f, int tid,
                                           u64& mask)
{
    for (int j = 0; j < 64; j += 4) {
        const float4* r0 = (const float4*)(Wl + (j + 0) * 64);
        const float4* r1 = (const float4*)(Wl + (j + 1) * 64);
        const float4* r2 = (const float4*)(Wl + (j + 2) * 64);
        const float4* r3 = (const float4*)(Wl + (j + 3) * 64);
        float a0 = w0l[j], a1 = w0l[j + 1], a2 = w0l[j + 2], a3 = w0l[j + 3];
        #pragma unroll
        for (int i = 0; i < 16; ++i) {
            float4 w0 = r0[i], w1 = r1[i], w2 = r2[i], w3 = r3[i];
            a0 = fmaf(w0.x, h[4*i], a0); a0 = fmaf(w0.y, h[4*i+1], a0);
            a0 = fmaf(w0.z, h[4*i+2], a0); a0 = fmaf(w0.w, h[4*i+3], a0);
            a1 = fmaf(w1.x, h[4*i], a1); a1 = fmaf(w1.y, h[4*i+1], a1);
            a1 = fmaf(w1.z, h[4*i+2], a1); a1 = fmaf(w1.w, h[4*i+3], a1);
            a2 = fmaf(w2.x, h[4*i], a2); a2 = fmaf(w2.y, h[4*i+1], a2);
            a2 = fmaf(w2.z, h[4*i+2], a2); a2 = fmaf(w2.w, h[4*i+3], a2);
            a3 = fmaf(w3.x, h[4*i], a3); a3 = fmaf(w3.y, h[4*i+1], a3);
            a3 = fmaf(w3.z, h[4*i+2], a3); a3 = fmaf(w3.w, h[4*i+3], a3);
        }
        float s0 = a0 + bl[j], s1 = a1 + bl[j + 1];
        float s2 = a2 + bl[j + 2], s3 = a3 + bl[j + 3];
        if (RELU) {
            bool p0 = s0 > 0.f, p1 = s1 > 0.f, p2 = s2 > 0.f, p3 = s3 > 0.f;
            s0 = p0 ? s0 : 0.f; s1 = p1 ? s1 : 0.f;
            s2 = p2 ? s2 : 0.f; s3 = p3 ? s3 : 0.f;
            u64 bits = (u64)p0 | ((u64)p1 << 1) | ((u64)p2 << 2) | ((u64)p3 << 3);
            mask |= bits << j;
        }
        int base = (j >> 1) * 256 + 2 * tid;    // [pair][2*tid + (j&1)] layout
        hb_f[base + 0]   = s0;  hb_f[base + 1]   = s1;
        hb_f[base + 256] = s2;  hb_f[base + 257] = s3;
    }
}

// Backward layer (saxpy, FFMA2): gout accumulators constant-indexed in the
// unrolled inner loop; per-j gradient from gmem (seed) or the smem slice.
template<bool MASK, bool FROM_GMEM>
__device__ __forceinline__ void bwd_layer(const float* __restrict__ Wl,
                                          const float* __restrict__ src_g,
                                          const float* hb_f, int tid,
                                          u64* gout, u64 mask)
{
    #pragma unroll
    for (int i = 0; i < 32; ++i) gout[i] = 0ull;
    for (int j = 0; j < 64; ++j) {
        float gj;
        if (FROM_GMEM) gj = __ldg(src_g + j);
        else           gj = hb_f[(j >> 1) * 256 + 2 * tid + (j & 1)];
        if (MASK) {
            u32 bit = (u32)((mask >> j) & 1ull);
            gj = bit ? gj : 0.f;
        }
        u64 g2 = pack2(gj, gj);
        const ulonglong2* wr = (const ulonglong2*)(Wl + j * 64);
        #pragma unroll
        for (int i = 0; i < 16; ++i) {
            ulonglong2 w = wr[i];
            gout[2*i]     = fma2(w.x, g2, gout[2*i]);
            gout[2*i + 1] = fma2(w.y, g2, gout[2*i + 1]);
        }
    }
}

__global__ void __launch_bounds__(128, 2) ode_hutch_kernel(
    const float* __restrict__ t,  const float* __restrict__ z,  const float* __restrict__ e,
    const float* __restrict__ W0, const float* __restrict__ b0,
    const float* __restrict__ W1, const float* __restrict__ b1,
    const float* __restrict__ W2, const float* __restrict__ b2,
    float* __restrict__ out, int B)
{
    float* Wsh  = smf;
    float* w0sh = smf + 12288;
    float* bsh  = smf + 12480;
    u64*   hb   = (u64*)(smf + 12672);
    float* hb_f = (float*)hb;
    int tid = threadIdx.x;

    float tval = t[0];
    for (int idx = tid; idx < 4096; idx += 128) {
        int j = idx >> 6, k = idx & 63;
        Wsh[idx]        = W0[j * 65 + 1 + k];
        Wsh[4096 + idx] = W1[j * 65 + 1 + k];
        Wsh[8192 + idx] = W2[j * 65 + 1 + k];
    }
    // Grid-strided (blockDim=128 < 192 entries!). w0sh = rn(t*W[j][0]) — the
    // serial chain's init term; bsh = bias, added after the k-sum (XLA order).
    for (int idx = tid; idx < 192; idx += 128) {
        int layer = idx >> 6, j = idx & 63;
        const float* Wg = (layer == 0) ? W0 : ((layer == 1) ? W1 : W2);
        const float* bg = (layer == 0) ? b0 : ((layer == 1) ? b1 : b2);
        w0sh[idx] = tval * Wg[j * 65];
        bsh[idx]  = bg[j];
    }
    __syncthreads();

    size_t row = (size_t)blockIdx.x * 128 + tid;
    if (row >= (size_t)B) return;

    float hreg[64];     // forward activations (constant-indexed only)
    u64   vbuf[32];     // backward accumulators (constant-indexed only)

    // ---- forward (order-matched serial chains) ----
    {
        const float4* zp = (const float4*)(z + row * 64);
        #pragma unroll
        for (int i = 0; i < 16; ++i) {
            float4 v = zp[i];
            hreg[4*i] = v.x; hreg[4*i+1] = v.y; hreg[4*i+2] = v.z; hreg[4*i+3] = v.w;
        }
    }

    u64 m0 = 0, m1 = 0, mdummy = 0;
    fwd_serial<true>(Wsh, w0sh, bsh, hreg, hb_f, tid, m0);              // z -> h1

    #pragma unroll
    for (int p = 0; p < 32; ++p) {
        u64 v = hb[p * 128 + tid]; hreg[2*p] = lo2(v); hreg[2*p+1] = hi2(v);
    }
    fwd_serial<true>(Wsh + 4096, w0sh + 64, bsh + 64, hreg, hb_f, tid, m1); // h1 -> h2

    #pragma unroll
    for (int p = 0; p < 32; ++p) {
        u64 v = hb[p * 128 + tid]; hreg[2*p] = lo2(v); hreg[2*p+1] = hi2(v);
    }
    fwd_serial<false>(Wsh + 8192, w0sh + 128, bsh + 128, hreg, hb_f, tid, mdummy); // h2 -> z_dot

    // z_dot: smem slice -> gmem
    ulonglong2* orow = (ulonglong2*)(out + row * 64);
    #pragma unroll
    for (int i = 0; i < 16; ++i)
        orow[i] = make_ulonglong2(hb[(2*i) * 128 + tid], hb[(2*i + 1) * 128 + tid]);

    // ---- backward (VJP, seed e) ----
    const float* erow = e + row * 64;
    bwd_layer<false, true >(Wsh + 8192, erow, hb_f, tid, vbuf, 0);   // g_h2
    #pragma unroll
    for (int p = 0; p < 32; ++p) hb[p * 128 + tid] = vbuf[p];
    bwd_layer<true,  false>(Wsh + 4096, erow, hb_f, tid, vbuf, m1);  // g_h1
    #pragma unroll
    for (int p = 0; p < 32; ++p) hb[p * 128 + tid] = vbuf[p];
    bwd_layer<true,  false>(Wsh,        erow, hb_f, tid, vbuf, m0);  // g_z

    // ---- div = sum(g_z * e) ----
    const ulonglong2* ep = (const ulonglong2*)(e + row * 64);
    u64 d0 = 0, d1 = 0;
    #pragma unroll
    for (int i = 0; i < 16; ++i) {
        ulonglong2 v = ep[i];
        d0 = fma2(vbuf[2*i],     v.x, d0);
        d1 = fma2(vbuf[2*i + 1], v.y, d1);
    }
    u64 ds = add2(d0, d1);
    out[(size_t)B * 64 + row] = -(lo2(ds) + hi2(ds));
}

static const int kSmemBytes = 12672 * 4 + 32 * 128 * 8;   // 50688 + 32768 = 83456

extern "C" void kernel_launch(void* const* d_in, const int* in_sizes, int n_in,
                              void* d_out, int out_size) {
    const float* t  = (const float*)d_in[0];
    const float* z  = (const float*)d_in[1];
    const float* e  = (const float*)d_in[2];
    const float* W0 = (const float*)d_in[3];
    const float* b0 = (const float*)d_in[4];
    const float* W1 = (const float*)d_in[5];
    const float* b1 = (const float*)d_in[6];
    const float* W2 = (const float*)d_in[7];
    const float* b2 = (const float*)d_in[8];
    float* out = (float*)d_out;

    cudaFuncSetAttribute(ode_hutch_kernel,
                         cudaFuncAttributeMaxDynamicSharedMemorySize, kSmemBytes);

    int B = in_sizes[1] / 64;          // z is [B, 64]
    int grid = (B + 127) / 128;
    ode_hutch_kernel<<<grid, 128, kSmemBytes>>>(t, z, e, W0, b0, W1, b1, W2, b2, out, B);
}

// round 14
// speedup vs baseline: 1.1956x; 1.1956x over previous
#include <cuda_runtime.h>

typedef unsigned long long u64;
typedef unsigned int u32;

// ---- packed fp32x2 helpers ----
__device__ __forceinline__ u64 fma2(u64 a, u64 b, u64 c) {
    u64 d; asm("fma.rn.f32x2 %0, %1, %2, %3;" : "=l"(d) : "l"(a), "l"(b), "l"(c)); return d;
}
__device__ __forceinline__ u64 add2(u64 a, u64 b) {
    u64 d; asm("add.rn.f32x2 %0, %1, %2;" : "=l"(d) : "l"(a), "l"(b)); return d;
}
__device__ __forceinline__ u64 pack2(float lo, float hi) {
    u64 d; asm("mov.b64 %0, {%1, %2};" : "=l"(d) : "f"(lo), "f"(hi)); return d;
}
__device__ __forceinline__ float lo2(u64 v) { return __uint_as_float((u32)v); }
__device__ __forceinline__ float hi2(u64 v) { return __uint_as_float((u32)(v >> 32)); }

// Dynamic smem: [0,12288) floats = W (3 layers, t-column stripped);
// then u64 hb[64][128] (64 KB) — row-pair-packed h/g buffer, thread-private slots.
extern __shared__ float smf[];

// Forward layer for TWO rows. Per row the arithmetic is IDENTICAL to the
// round-7 bit-exact serial chain: acc = rn(t*W[j][0]); 64 serial fmaf with k
// ascending; + b[j]; relu. The two rows are independent scalar chains that
// share each W float4 load. j-loop rolled (no register array touched by j).
template<bool RELU>
__device__ __forceinline__ void fwd2(const float* __restrict__ Wl,
                                     const float* __restrict__ Wg,   // original [64][65]
                                     const float* __restrict__ bl,
                                     float tval,
                                     const float* h0, const float* h1,
                                     u64* hb, int tid, u64& m_r0, u64& m_r1)
{
    for (int j = 0; j < 64; j += 2) {
        const float4* ra = (const float4*)(Wl + j * 64);
        const float4* rb = (const float4*)(Wl + (j + 1) * 64);
        float a0 = tval * __ldg(Wg + j * 65);        // uniform L1-hit
        float a1 = tval * __ldg(Wg + (j + 1) * 65);
        float c0 = a0, c1 = a1;                       // row1 chains, same init
        #pragma unroll
        for (int i = 0; i < 16; ++i) {
            float4 wa = ra[i], wb = rb[i];            // shared by both rows
            a0 = fmaf(wa.x, h0[4*i],   a0); a0 = fmaf(wa.y, h0[4*i+1], a0);
            a0 = fmaf(wa.z, h0[4*i+2], a0); a0 = fmaf(wa.w, h0[4*i+3], a0);
            c0 = fmaf(wa.x, h1[4*i],   c0); c0 = fmaf(wa.y, h1[4*i+1], c0);
            c0 = fmaf(wa.z, h1[4*i+2], c0); c0 = fmaf(wa.w, h1[4*i+3], c0);
            a1 = fmaf(wb.x, h0[4*i],   a1); a1 = fmaf(wb.y, h0[4*i+1], a1);
            a1 = fmaf(wb.z, h0[4*i+2], a1); a1 = fmaf(wb.w, h0[4*i+3], a1);
            c1 = fmaf(wb.x, h1[4*i],   c1); c1 = fmaf(wb.y, h1[4*i+1], c1);
            c1 = fmaf(wb.z, h1[4*i+2], c1); c1 = fmaf(wb.w, h1[4*i+3], c1);
        }
        float bja = __ldg(bl + j), bjb = __ldg(bl + j + 1);
        float s00 = a0 + bja, s10 = c0 + bja;         // (j,row0) (j,row1)
        float s01 = a1 + bjb, s11 = c1 + bjb;         // (j+1,row0) (j+1,row1)
        if (RELU) {
            bool p00 = s00 > 0.f, p10 = s10 > 0.f, p01 = s01 > 0.f, p11 = s11 > 0.f;
            s00 = p00 ? s00 : 0.f; s10 = p10 ? s10 : 0.f;
            s01 = p01 ? s01 : 0.f; s11 = p11 ? s11 : 0.f;
            m_r0 |= ((u64)p00 << j) | ((u64)p01 << (j + 1));
            m_r1 |= ((u64)p10 << j) | ((u64)p11 << (j + 1));
        }
        hb[j * 128 + tid]       = pack2(s00, s10);    // STS.64, thread-private
        hb[(j + 1) * 128 + tid] = pack2(s01, s11);
    }
}

// Backward seed: g = e @ W2' for both rows; e streamed as float4 (4 j per load).
__device__ __forceinline__ void bwd_seed(const float* __restrict__ Wl,
                                         const float4* __restrict__ e4_0,
                                         const float4* __restrict__ e4_1,
                                         u64* g0, u64* g1)
{
    #pragma unroll
    for (int p = 0; p < 32; ++p) { g0[p] = 0ull; g1[p] = 0ull; }
    for (int jq = 0; jq < 16; ++jq) {
        float4 ea = __ldg(e4_0 + jq);
        float4 eb = __ldg(e4_1 + jq);
        #pragma unroll
        for (int s = 0; s < 4; ++s) {
            int j = jq * 4 + s;
            float ga = (s == 0) ? ea.x : (s == 1) ? ea.y : (s == 2) ? ea.z : ea.w;
            float gb = (s == 0) ? eb.x : (s == 1) ? eb.y : (s == 2) ? eb.z : eb.w;
            u64 pa = pack2(ga, ga), pb = pack2(gb, gb);
            const ulonglong2* wr = (const ulonglong2*)(Wl + j * 64);
            #pragma unroll
            for (int i = 0; i < 16; ++i) {
                ulonglong2 w = wr[i];                  // shared by both rows
                g0[2*i]   = fma2(w.x, pa, g0[2*i]);
                g0[2*i+1] = fma2(w.y, pa, g0[2*i+1]);
                g1[2*i]   = fma2(w.x, pb, g1[2*i]);
                g1[2*i+1] = fma2(w.y, pb, g1[2*i+1]);
            }
        }
    }
}

// Backward middle layer: g_out = (g_in ∘ mask) @ Wl' for both rows.
// g_in read from hb (row0 at slots [0..31], row1 at [32..63]).
__device__ __forceinline__ void bwd_mid(const float* __restrict__ Wl,
                                        const u64* hbg, int tid,
                                        u64 m_r0, u64 m_r1,
                                        u64* g0, u64* g1)
{
    #pragma unroll
    for (int p = 0; p < 32; ++p) { g0[p] = 0ull; g1[p] = 0ull; }
    for (int jp = 0; jp < 32; ++jp) {
        u64 va = hbg[jp * 128 + tid];          // (g_{2jp}, g_{2jp+1}) row0
        u64 vb = hbg[(32 + jp) * 128 + tid];   // row1
        int j0 = 2 * jp, j1 = 2 * jp + 1;
        float ga0 = lo2(va), ga1 = hi2(va);
        float gb0 = lo2(vb), gb1 = hi2(vb);
        ga0 = ((m_r0 >> j0) & 1ull) ? ga0 : 0.f;
        ga1 = ((m_r0 >> j1) & 1ull) ? ga1 : 0.f;
        gb0 = ((m_r1 >> j0) & 1ull) ? gb0 : 0.f;
        gb1 = ((m_r1 >> j1) & 1ull) ? gb1 : 0.f;
        u64 pa0 = pack2(ga0, ga0), pa1 = pack2(ga1, ga1);
        u64 pb0 = pack2(gb0, gb0), pb1 = pack2(gb1, gb1);
        const ulonglong2* wr0 = (const ulonglong2*)(Wl + j0 * 64);
        const ulonglong2* wr1 = (const ulonglong2*)(Wl + j1 * 64);
        #pragma unroll
        for (int i = 0; i < 16; ++i) {
            ulonglong2 w0 = wr0[i], w1 = wr1[i];
            g0[2*i]   = fma2(w0.x, pa0, g0[2*i]);
            g0[2*i+1] = fma2(w0.y, pa0, g0[2*i+1]);
            g1[2*i]   = fma2(w0.x, pb0, g1[2*i]);
            g1[2*i+1] = fma2(w0.y, pb0, g1[2*i+1]);
            g0[2*i]   = fma2(w1.x, pa1, g0[2*i]);
            g0[2*i+1] = fma2(w1.y, pa1, g0[2*i+1]);
            g1[2*i]   = fma2(w1.x, pb1, g1[2*i]);
            g1[2*i+1] = fma2(w1.y, pb1, g1[2*i+1]);
        }
    }
}

__global__ void __launch_bounds__(128, 2) ode_hutch_kernel(
    const float* __restrict__ t,  const float* __restrict__ z,  const float* __restrict__ e,
    const float* __restrict__ W0, const float* __restrict__ b0,
    const float* __restrict__ W1, const float* __restrict__ b1,
    const float* __restrict__ W2, const float* __restrict__ b2,
    float* __restrict__ out, int B)
{
    float* Wsh = smf;
    u64*   hb  = (u64*)(smf + 12288);
    int tid = threadIdx.x;

    float tval = t[0];
    for (int idx = tid; idx < 4096; idx += 128) {
        int j = idx >> 6, k = idx & 63;
        Wsh[idx]        = W0[j * 65 + 1 + k];
        Wsh[4096 + idx] = W1[j * 65 + 1 + k];
        Wsh[8192 + idx] = W2[j * 65 + 1 + k];
    }
    __syncthreads();

    size_t row0 = (size_t)blockIdx.x * 256 + tid;
    if (row0 >= (size_t)B) return;
    size_t row1 = row0 + 128;
    bool r1ok = row1 < (size_t)B;
    size_t row1c = r1ok ? row1 : row0;

    float h0[64], h1[64];        // two rows' activations (constant-indexed)
    {
        const float4* z0 = (const float4*)(z + row0 * 64);
        const float4* z1 = (const float4*)(z + row1c * 64);
        #pragma unroll
        for (int i = 0; i < 16; ++i) {
            float4 v = __ldg(z0 + i), w = __ldg(z1 + i);
            h0[4*i] = v.x; h0[4*i+1] = v.y; h0[4*i+2] = v.z; h0[4*i+3] = v.w;
            h1[4*i] = w.x; h1[4*i+1] = w.y; h1[4*i+2] = w.z; h1[4*i+3] = w.w;
        }
    }

    u64 m0_r0 = 0, m0_r1 = 0, m1_r0 = 0, m1_r1 = 0, du0 = 0, du1 = 0;
    fwd2<true>(Wsh, W0, b0, tval, h0, h1, hb, tid, m0_r0, m0_r1);     // z -> h1

    #pragma unroll
    for (int k = 0; k < 64; ++k) { u64 v = hb[k*128 + tid]; h0[k] = lo2(v); h1[k] = hi2(v); }
    fwd2<true>(Wsh + 4096, W1, b1, tval, h0, h1, hb, tid, m1_r0, m1_r1); // -> h2

    #pragma unroll
    for (int k = 0; k < 64; ++k) { u64 v = hb[k*128 + tid]; h0[k] = lo2(v); h1[k] = hi2(v); }
    fwd2<false>(Wsh + 8192, W2, b2, tval, h0, h1, hb, tid, du0, du1);    // -> z_dot

    #pragma unroll
    for (int k = 0; k < 64; ++k) { u64 v = hb[k*128 + tid]; h0[k] = lo2(v); h1[k] = hi2(v); }
    {
        float4* o0 = (float4*)(out + row0 * 64);
        #pragma unroll
        for (int i = 0; i < 16; ++i)
            o0[i] = make_float4(h0[4*i], h0[4*i+1], h0[4*i+2], h0[4*i+3]);
        if (r1ok) {
            float4* o1 = (float4*)(out + row1 * 64);
            #pragma unroll
            for (int i = 0; i < 16; ++i)
                o1[i] = make_float4(h1[4*i], h1[4*i+1], h1[4*i+2], h1[4*i+3]);
        }
    }

    // ---- backward (VJP, seed e) ----
    u64 g0[32], g1[32];
    bwd_seed(Wsh + 8192, (const float4*)(e + row0 * 64),
             (const float4*)(e + row1c * 64), g0, g1);                 // g_h2
    #pragma unroll
    for (int p = 0; p < 32; ++p) { hb[p*128 + tid] = g0[p]; hb[(32+p)*128 + tid] = g1[p]; }
    bwd_mid(Wsh + 4096, hb, tid, m1_r0, m1_r1, g0, g1);                // g_h1
    #pragma unroll
    for (int p = 0; p < 32; ++p) { hb[p*128 + tid] = g0[p]; hb[(32+p)*128 + tid] = g1[p]; }
    bwd_mid(Wsh, hb, tid, m0_r0, m0_r1, g0, g1);                       // g_z

    // ---- div = sum(g_z * e) per row ----
    {
        const float4* e0 = (const float4*)(e + row0 * 64);
        const float4* e1 = (const float4*)(e + row1c * 64);
        u64 d0a = 0, d0b = 0, d1a = 0, d1b = 0;
        #pragma unroll
        for (int i = 0; i < 16; ++i) {
            float4 va = __ldg(e0 + i), vb = __ldg(e1 + i);
            d0a = fma2(g0[2*i],   pack2(va.x, va.y), d0a);
            d0b = fma2(g0[2*i+1], pack2(va.z, va.w), d0b);
            d1a = fma2(g1[2*i],   pack2(vb.x, vb.y), d1a);
            d1b = fma2(g1[2*i+1], pack2(vb.z, vb.w), d1b);
        }
        u64 s0 = add2(d0a, d0b), s1 = add2(d1a, d1b);
        out[(size_t)B * 64 + row0] = -(lo2(s0) + hi2(s0));
        if (r1ok) out[(size_t)B * 64 + row1] = -(lo2(s1) + hi2(s1));
    }
}

static const int kSmemBytes = 12288 * 4 + 64 * 128 * 8;   // 49152 + 65536 = 114688

extern "C" void kernel_launch(void* const* d_in, const int* in_sizes, int n_in,
                              void* d_out, int out_size) {
    const float* t  = (const float*)d_in[0];
    const float* z  = (const float*)d_in[1];
    const float* e  = (const float*)d_in[2];
    const float* W0 = (const float*)d_in[3];
    const float* b0 = (const float*)d_in[4];
    const float* W1 = (const float*)d_in[5];
    const float* b1 = (const float*)d_in[6];
    const float* W2 = (const float*)d_in[7];
    const float* b2 = (const float*)d_in[8];
    float* out = (float*)d_out;

    cudaFuncSetAttribute(ode_hutch_kernel,
                         cudaFuncAttributeMaxDynamicSharedMemorySize, kSmemBytes);

    int B = in_sizes[1] / 64;          // z is [B, 64]
    int grid = (B + 255) / 256;        // 256 rows per CTA (2 per thread)
    ode_hutch_kernel<<<grid, 128, kSmemBytes>>>(t, z, e, W0, b0, W1, b1, W2, b2, out, B);
}